// round 1
// baseline (speedup 1.0000x reference)
#include <cuda_runtime.h>
#include <cuda_bf16.h>
#include <math.h>

// ---------------------------------------------------------------------------
// SINDy autoencoder, fp32 baseline.
// Pipeline:
//  K1 wide_layer<K=64>        : x0 @ enc_W1 + b -> LN -> SiLU        -> g_h1
//  K2 wide_layer<K=512,Z>     : g_h1 @ enc_W2 + b -> LN -> SiLU
//                               (fused) @ enc_W3 + b3 -> tanh        -> g_z0
//  K3 integrate               : 20 Euler steps of Theta(z) @ Xi      -> g_zt
//  K4 wide_layer<K=8>         : g_zt @ dec_W1 + b -> LN -> SiLU      -> g_h1
//  K5 wide_layer<K=512>       : g_h1 @ dec_W2 + b -> LN -> SiLU      -> g_h2
//  K6 out_layer               : g_h2 @ dec_W3 + b3                   -> d_out
// ---------------------------------------------------------------------------

#define BATCH   131072
#define NX      64
#define HID     512
#define LDIM    8
#define NTH     45
#define NSTEPS  20

// scratch (allocation-free rule: __device__ globals)
__device__ float g_h1[BATCH * HID];
__device__ float g_h2[BATCH * HID];
__device__ float g_z0[BATCH * LDIM];
__device__ float g_zt[BATCH * LDIM];

// ---------------------------------------------------------------------------
// wide_layer: C[B,512] = act(LN(A[B,K] @ W[K,512] + b))   (act = SiLU)
// BM=64 rows/block, BN=512 (full row -> LN in one pass), BK = 16 (or 8).
// 256 threads: ty = warp (8 row-group), tx = lane (column group).
// Thread owns rows ty*8..ty*8+7 and cols {tx*4 + 128*j + v : j<4, v<4}.
// If WRITE_Z: instead of storing h, fuse  z = tanh(h @ W3[512,8] + b3).
// ---------------------------------------------------------------------------
template<int K, int BK, bool WRITE_Z>
__global__ __launch_bounds__(256, 1)
void wide_layer_kernel(const float* __restrict__ A,
                       const float* __restrict__ W,
                       const float* __restrict__ bias,
                       const float* __restrict__ gamma,
                       const float* __restrict__ beta,
                       float* __restrict__ outH,
                       const float* __restrict__ W3,
                       const float* __restrict__ b3,
                       float* __restrict__ outZ)
{
    extern __shared__ float sm[];
    float* As  = sm;                 // [BK][64]  (transposed A tile)
    float* Bs  = sm + BK * 64;       // [BK][512]
    float* W3s = Bs + BK * 512;      // [512][8]  only when WRITE_Z

    const int tid = threadIdx.x;
    const int ty  = tid >> 5;        // 0..7
    const int tx  = tid & 31;        // 0..31
    const int row0 = blockIdx.x * 64;

    if (WRITE_Z) {
        for (int i = tid; i < (HID * LDIM) / 4; i += 256)
            ((float4*)W3s)[i] = ((const float4*)W3)[i];
    }

    float acc[8][16];
#pragma unroll
    for (int i = 0; i < 8; i++)
#pragma unroll
        for (int t = 0; t < 16; t++) acc[i][t] = 0.f;

    for (int k0 = 0; k0 < K; k0 += BK) {
        __syncthreads();
        // --- A tile (transposed): 64 rows x BK cols ---
        for (int idx = tid; idx < 16 * BK; idx += 256) {
            const int r  = idx / (BK / 4);
            const int kq = idx % (BK / 4);
            float4 a = *(const float4*)(A + (size_t)(row0 + r) * K + k0 + kq * 4);
            As[(kq * 4 + 0) * 64 + r] = a.x;
            As[(kq * 4 + 1) * 64 + r] = a.y;
            As[(kq * 4 + 2) * 64 + r] = a.z;
            As[(kq * 4 + 3) * 64 + r] = a.w;
        }
        // --- B tile: BK rows x 512 cols ---
        for (int idx = tid; idx < 128 * BK; idx += 256) {
            const int r = idx >> 7;
            const int c = idx & 127;
            *(float4*)(Bs + r * 512 + c * 4) =
                *(const float4*)(W + (size_t)(k0 + r) * 512 + c * 4);
        }
        __syncthreads();

#pragma unroll
        for (int k = 0; k < BK; k++) {
            float av[8];
            *(float4*)&av[0] = *(const float4*)(As + k * 64 + ty * 8);
            *(float4*)&av[4] = *(const float4*)(As + k * 64 + ty * 8 + 4);
            float bv[16];
#pragma unroll
            for (int j = 0; j < 4; j++)
                *(float4*)&bv[j * 4] = *(const float4*)(Bs + k * 512 + tx * 4 + j * 128);
#pragma unroll
            for (int i = 0; i < 8; i++)
#pragma unroll
                for (int t = 0; t < 16; t++)
                    acc[i][t] = fmaf(av[i], bv[t], acc[i][t]);
        }
    }

    // ------------------------- epilogue: bias + LN + SiLU -------------------
    float bb[16], gg[16], be[16];
#pragma unroll
    for (int j = 0; j < 4; j++)
#pragma unroll
        for (int v = 0; v < 4; v++) {
            const int c = tx * 4 + j * 128 + v;
            bb[j * 4 + v] = __ldg(bias + c);
            gg[j * 4 + v] = __ldg(gamma + c);
            be[j * 4 + v] = __ldg(beta + c);
        }

#pragma unroll
    for (int i = 0; i < 8; i++) {
        float s = 0.f, s2 = 0.f;
#pragma unroll
        for (int t = 0; t < 16; t++) {
            float v = acc[i][t] + bb[t];
            acc[i][t] = v;
            s += v; s2 += v * v;
        }
#pragma unroll
        for (int o = 16; o; o >>= 1) {
            s  += __shfl_xor_sync(0xffffffffu, s, o);
            s2 += __shfl_xor_sync(0xffffffffu, s2, o);
        }
        const float mean = s * (1.f / 512.f);
        const float var  = s2 * (1.f / 512.f) - mean * mean;
        const float rstd = rsqrtf(var + 1e-5f);
#pragma unroll
        for (int t = 0; t < 16; t++) {
            float v = (acc[i][t] - mean) * rstd * gg[t] + be[t];
            acc[i][t] = v * (1.f / (1.f + __expf(-v)));   // SiLU
        }
        if (!WRITE_Z) {
            const size_t r = (size_t)(row0 + ty * 8 + i);
#pragma unroll
            for (int j = 0; j < 4; j++)
                *(float4*)(outH + r * 512 + tx * 4 + j * 128) = *(float4*)&acc[i][j * 4];
        }
    }

    if (WRITE_Z) {
        // fused: z0 = tanh(h @ W3 + b3), h distributed over the warp
        float zacc[8][8];
#pragma unroll
        for (int i = 0; i < 8; i++)
#pragma unroll
            for (int j = 0; j < 8; j++) zacc[i][j] = 0.f;

#pragma unroll
        for (int t = 0; t < 16; t++) {
            const int c = tx * 4 + (t >> 2) * 128 + (t & 3);
            float w[8];
            *(float4*)&w[0] = *(const float4*)(W3s + c * 8);
            *(float4*)&w[4] = *(const float4*)(W3s + c * 8 + 4);
#pragma unroll
            for (int i = 0; i < 8; i++)
#pragma unroll
                for (int j = 0; j < 8; j++)
                    zacc[i][j] = fmaf(acc[i][t], w[j], zacc[i][j]);
        }
#pragma unroll
        for (int i = 0; i < 8; i++)
#pragma unroll
            for (int j = 0; j < 8; j++)
#pragma unroll
                for (int o = 16; o; o >>= 1)
                    zacc[i][j] += __shfl_xor_sync(0xffffffffu, zacc[i][j], o);
        if (tx < 8) {
            const float b3v = __ldg(b3 + tx);
#pragma unroll
            for (int i = 0; i < 8; i++) {
                const size_t r = (size_t)(row0 + ty * 8 + i);
                outZ[r * 8 + tx] = tanhf(zacc[i][tx] + b3v);
            }
        }
    }
}

// ---------------------------------------------------------------------------
// integrator: 20 Euler steps of dz = (Theta(z) @ Xi) * dt, dt = Dt[row]/20.
// 2 rows per thread so each Xi value loaded from smem is reused twice.
// ---------------------------------------------------------------------------
__global__ __launch_bounds__(256, 4)
void integrate_kernel(const float* __restrict__ z0,
                      const float* __restrict__ dtv,
                      const float* __restrict__ Xi,
                      float* __restrict__ zt)
{
    __shared__ float Xis[NTH * LDIM];
    for (int i = threadIdx.x; i < NTH * LDIM; i += 256) Xis[i] = Xi[i];
    __syncthreads();

    const size_t base = ((size_t)blockIdx.x * 256 + threadIdx.x) * 2;
    float z[2][8], dt[2];
#pragma unroll
    for (int r = 0; r < 2; r++) {
        *(float4*)&z[r][0] = *(const float4*)(z0 + (base + r) * 8);
        *(float4*)&z[r][4] = *(const float4*)(z0 + (base + r) * 8 + 4);
        dt[r] = dtv[base + r] * (1.f / (float)NSTEPS);
    }

#pragma unroll 1
    for (int s = 0; s < NSTEPS; s++) {
        float zd[2][8];
#pragma unroll
        for (int j = 0; j < 8; j++) { zd[0][j] = Xis[j]; zd[1][j] = Xis[j]; } // theta_0 = 1
        // linear terms
#pragma unroll
        for (int i = 0; i < 8; i++) {
            const float t0 = z[0][i], t1 = z[1][i];
#pragma unroll
            for (int j = 0; j < 8; j++) {
                const float x = Xis[(1 + i) * 8 + j];
                zd[0][j] = fmaf(t0, x, zd[0][j]);
                zd[1][j] = fmaf(t1, x, zd[1][j]);
            }
        }
        // quadratic (upper-tri, row-wise: matches np.triu_indices)
        int idx = 9;
#pragma unroll
        for (int i = 0; i < 8; i++)
#pragma unroll
            for (int k = i; k < 8; k++) {
                const float q0 = z[0][i] * z[0][k];
                const float q1 = z[1][i] * z[1][k];
#pragma unroll
                for (int j = 0; j < 8; j++) {
                    const float x = Xis[idx * 8 + j];
                    zd[0][j] = fmaf(q0, x, zd[0][j]);
                    zd[1][j] = fmaf(q1, x, zd[1][j]);
                }
                idx++;
            }
#pragma unroll
        for (int r = 0; r < 2; r++)
#pragma unroll
            for (int j = 0; j < 8; j++)
                z[r][j] = fmaf(zd[r][j], dt[r], z[r][j]);
    }

#pragma unroll
    for (int r = 0; r < 2; r++) {
        *(float4*)(zt + (base + r) * 8)     = *(float4*)&z[r][0];
        *(float4*)(zt + (base + r) * 8 + 4) = *(float4*)&z[r][4];
    }
}

// ---------------------------------------------------------------------------
// out_layer: out[B,64] = A[B,512] @ W[512,64] + b.  BM=64, BN=64, BK=16.
// 256 threads, 4x4 register tile each.
// ---------------------------------------------------------------------------
__global__ __launch_bounds__(256, 2)
void out_layer_kernel(const float* __restrict__ A,
                      const float* __restrict__ W,
                      const float* __restrict__ bias,
                      float* __restrict__ out)
{
    __shared__ float As[16 * 64];   // transposed A tile
    __shared__ float Bs[16 * 64];
    const int tid = threadIdx.x;
    const int ty  = tid >> 4;       // 0..15 (row group of 4)
    const int tx  = tid & 15;       // 0..15 (col group of 4)
    const int row0 = blockIdx.x * 64;

    float acc[4][4];
#pragma unroll
    for (int i = 0; i < 4; i++)
#pragma unroll
        for (int j = 0; j < 4; j++) acc[i][j] = 0.f;

    for (int k0 = 0; k0 < 512; k0 += 16) {
        __syncthreads();
        {   // A: one float4 per thread along K, store transposed
            const int r  = tid >> 2;
            const int kq = tid & 3;
            float4 a = *(const float4*)(A + (size_t)(row0 + r) * 512 + k0 + kq * 4);
            As[(kq * 4 + 0) * 64 + r] = a.x;
            As[(kq * 4 + 1) * 64 + r] = a.y;
            As[(kq * 4 + 2) * 64 + r] = a.z;
            As[(kq * 4 + 3) * 64 + r] = a.w;
        }
        {   // B: one float4 per thread
            const int r = tid >> 4;
            const int c = tid & 15;
            *(float4*)(Bs + r * 64 + c * 4) =
                *(const float4*)(W + (size_t)(k0 + r) * 64 + c * 4);
        }
        __syncthreads();
#pragma unroll
        for (int k = 0; k < 16; k++) {
            float4 a = *(const float4*)(As + k * 64 + ty * 4);
            float4 b = *(const float4*)(Bs + k * 64 + tx * 4);
            const float av[4] = {a.x, a.y, a.z, a.w};
            const float bv[4] = {b.x, b.y, b.z, b.w};
#pragma unroll
            for (int i = 0; i < 4; i++)
#pragma unroll
                for (int j = 0; j < 4; j++)
                    acc[i][j] = fmaf(av[i], bv[j], acc[i][j]);
        }
    }

    float4 bv = *(const float4*)(bias + tx * 4);
#pragma unroll
    for (int i = 0; i < 4; i++) {
        const size_t r = (size_t)(row0 + ty * 4 + i);
        float4 o;
        o.x = acc[i][0] + bv.x;
        o.y = acc[i][1] + bv.y;
        o.z = acc[i][2] + bv.z;
        o.w = acc[i][3] + bv.w;
        *(float4*)(out + r * 64 + tx * 4) = o;
    }
}

// ---------------------------------------------------------------------------
extern "C" void kernel_launch(void* const* d_in, const int* in_sizes, int n_in,
                              void* d_out, int out_size)
{
    (void)in_sizes; (void)n_in; (void)out_size;
    const float* x0   = (const float*)d_in[0];
    const float* dtn  = (const float*)d_in[1];
    // d_in[2], d_in[3] : Dt_mean / Dt_std (unused by reference)
    const float* eW1  = (const float*)d_in[4];
    const float* eb1  = (const float*)d_in[5];
    const float* eg1  = (const float*)d_in[6];
    const float* ebe1 = (const float*)d_in[7];
    const float* eW2  = (const float*)d_in[8];
    const float* eb2  = (const float*)d_in[9];
    const float* eg2  = (const float*)d_in[10];
    const float* ebe2 = (const float*)d_in[11];
    const float* eW3  = (const float*)d_in[12];
    const float* eb3  = (const float*)d_in[13];
    const float* dW1  = (const float*)d_in[14];
    const float* db1  = (const float*)d_in[15];
    const float* dg1  = (const float*)d_in[16];
    const float* dbe1 = (const float*)d_in[17];
    const float* dW2  = (const float*)d_in[18];
    const float* db2  = (const float*)d_in[19];
    const float* dg2  = (const float*)d_in[20];
    const float* dbe2 = (const float*)d_in[21];
    const float* dW3  = (const float*)d_in[22];
    const float* db3  = (const float*)d_in[23];
    const float* Xi   = (const float*)d_in[24];
    float* out = (float*)d_out;

    float *h1, *h2, *z0, *zt;
    cudaGetSymbolAddress((void**)&h1, g_h1);
    cudaGetSymbolAddress((void**)&h2, g_h2);
    cudaGetSymbolAddress((void**)&z0, g_z0);
    cudaGetSymbolAddress((void**)&zt, g_zt);

    const size_t smem_k64  = (16 * 64 + 16 * 512) * sizeof(float);             // 36864
    const size_t smem_k512z = smem_k64 + HID * LDIM * sizeof(float);           // 53248
    const size_t smem_k8   = (8 * 64 + 8 * 512) * sizeof(float);               // 18432

    cudaFuncSetAttribute(wide_layer_kernel<512, 16, true>,
                         cudaFuncAttributeMaxDynamicSharedMemorySize, (int)smem_k512z);
    cudaFuncSetAttribute(wide_layer_kernel<512, 16, false>,
                         cudaFuncAttributeMaxDynamicSharedMemorySize, (int)smem_k64);
    cudaFuncSetAttribute(wide_layer_kernel<64, 16, false>,
                         cudaFuncAttributeMaxDynamicSharedMemorySize, (int)smem_k64);
    cudaFuncSetAttribute(wide_layer_kernel<8, 8, false>,
                         cudaFuncAttributeMaxDynamicSharedMemorySize, (int)smem_k8);

    const int nblk = BATCH / 64;   // 2048

    // encoder layer 1
    wide_layer_kernel<64, 16, false><<<nblk, 256, smem_k64>>>(
        x0, eW1, eb1, eg1, ebe1, h1, nullptr, nullptr, nullptr);
    // encoder layer 2 + fused layer 3 (-> z0)
    wide_layer_kernel<512, 16, true><<<nblk, 256, smem_k512z>>>(
        h1, eW2, eb2, eg2, ebe2, nullptr, eW3, eb3, z0);
    // latent integrator
    integrate_kernel<<<BATCH / 512, 256>>>(z0, dtn, Xi, zt);
    // decoder layer 1
    wide_layer_kernel<8, 8, false><<<nblk, 256, smem_k8>>>(
        zt, dW1, db1, dg1, dbe1, h1, nullptr, nullptr, nullptr);
    // decoder layer 2
    wide_layer_kernel<512, 16, false><<<nblk, 256, smem_k64>>>(
        h1, dW2, db2, dg2, dbe2, h2, nullptr, nullptr, nullptr);
    // decoder output layer
    out_layer_kernel<<<nblk, 256>>>(h2, dW3, db3, out);
}

// round 5
// speedup vs baseline: 1.7943x; 1.7943x over previous
#include <cuda_runtime.h>
#include <cuda_bf16.h>
#include <math.h>
#include <stdint.h>

#define BATCH   131072
#define HID     512
#define LDIM    8
#define NTH     45
#define NSTEPS  20

// ============================================================================
// Baseline-PTX tensor helpers (compute_103-safe: ldmatrix + mma.sync only)
// ============================================================================
__device__ __forceinline__ uint32_t smem_u32(const void* p) {
    uint32_t a;
    asm("{ .reg .u64 t; cvta.to.shared.u64 t, %1; cvt.u32.u64 %0, t; }"
        : "=r"(a) : "l"(p));
    return a;
}

#define LDSM4(r0, r1, r2, r3, addr) \
    asm volatile("ldmatrix.sync.aligned.m8n8.x4.shared.b16 {%0,%1,%2,%3}, [%4];" \
        : "=r"(r0), "=r"(r1), "=r"(r2), "=r"(r3) : "r"(addr))

#define MMA16816(d, a, b0, b1) \
    asm volatile("mma.sync.aligned.m16n8k16.row.col.f32.bf16.bf16.f32 " \
        "{%0,%1,%2,%3},{%4,%5,%6,%7},{%8,%9},{%0,%1,%2,%3};" \
        : "+f"((d)[0]), "+f"((d)[1]), "+f"((d)[2]), "+f"((d)[3]) \
        : "r"((a)[0]), "r"((a)[1]), "r"((a)[2]), "r"((a)[3]), \
          "r"(b0), "r"(b1))

__device__ __forceinline__ void cp16(uint32_t dst, const void* src) {
    asm volatile("cp.async.cg.shared.global [%0], [%1], 16;"
        :: "r"(dst), "l"(src));
}
#define CP_COMMIT() asm volatile("cp.async.commit_group;" ::: "memory")
#define CP_WAIT(n)  asm volatile("cp.async.wait_group %0;" :: "n"(n) : "memory")

__device__ __forceinline__ uint32_t pack_bf2(float a, float b) {
    __nv_bfloat162 t = __floats2bfloat162_rn(a, b);
    return reinterpret_cast<uint32_t&>(t);
}
__device__ __forceinline__ float bf_lo(uint32_t u) {
    return __bfloat162float(__ushort_as_bfloat16((unsigned short)(u & 0xffffu)));
}
__device__ __forceinline__ float bf_hi(uint32_t u) {
    return __bfloat162float(__ushort_as_bfloat16((unsigned short)(u >> 16)));
}

// ============================================================================
// Scratch (allocation-free rule): activations as row-major bf16 hi/lo pairs.
// ============================================================================
__device__ __nv_bfloat16 g_hA_hi[BATCH * HID], g_hA_lo[BATCH * HID];
__device__ __nv_bfloat16 g_hB_hi[BATCH * HID], g_hB_lo[BATCH * HID];
__device__ __nv_bfloat16 g_x_hi[BATCH * 64],   g_x_lo[BATCH * 64];
__device__ __nv_bfloat16 g_z_hi[BATCH * 32],   g_z_lo[BATCH * 32];  // zt pad 32
__device__ float         g_z0[BATCH * LDIM];

// Weights pre-transposed WT[n][kpad] (row-major), split hi/lo, zero-pad k>=K
__device__ __nv_bfloat16 g_w1_hi[512 * 64],  g_w1_lo[512 * 64];    // enc_W1
__device__ __nv_bfloat16 g_w2_hi[512 * 512], g_w2_lo[512 * 512];   // enc_W2
__device__ __nv_bfloat16 g_d1_hi[512 * 32],  g_d1_lo[512 * 32];    // dec_W1 (K=8 pad 32)
__device__ __nv_bfloat16 g_d2_hi[512 * 512], g_d2_lo[512 * 512];   // dec_W2
__device__ __nv_bfloat16 g_d3_hi[64 * 512],  g_d3_lo[64 * 512];    // dec_W3

// ============================================================================
// prep kernels
// ============================================================================
__global__ void prep_wT_kernel(const float* __restrict__ W, int K, int N, int KPAD,
                               int total, __nv_bfloat16* __restrict__ hi,
                               __nv_bfloat16* __restrict__ lo)
{
    int idx = blockIdx.x * 256 + threadIdx.x;
    if (idx >= total) return;
    int n = idx / KPAD, k = idx % KPAD;
    float v = (k < K) ? W[(size_t)k * N + n] : 0.f;
    float h = __bfloat162float(__float2bfloat16(v));
    hi[idx] = __float2bfloat16(h);
    lo[idx] = __float2bfloat16(v - h);
}

__global__ void prep_x_kernel(const float* __restrict__ x0,
                              __nv_bfloat16* __restrict__ hi,
                              __nv_bfloat16* __restrict__ lo)
{
    size_t idx = (size_t)blockIdx.x * 256 + threadIdx.x;
    float v = x0[idx];
    float h = __bfloat162float(__float2bfloat16(v));
    hi[idx] = __float2bfloat16(h);
    lo[idx] = __float2bfloat16(v - h);
}

// ============================================================================
// wide layer: O[B,512] = SiLU(LN(A[B,KPAD] @ W + b)), bf16x3 split MMA.
// CTA: M=64 rows, N=512 (full row -> fused LN). 512 threads = 16 warps,
// warp grid 2(M) x 8(N), warp tile m32 x n64. BK=32, cp.async double buffer.
// smem rows padded to 80B -> conflict-free ldmatrix.
// ============================================================================
#define LDR 80                     // padded smem row bytes (40 bf16)
#define SA_HI 0                    // 2 x (64*80)   = 10240
#define SA_LO 10240                // 2 x (64*80)   = 10240
#define SB_HI 20480                // 2 x (512*80)  = 81920
#define SB_LO 102400               // 2 x (512*80)  = 81920
#define SPAR  184320               // bias/g/beta 3x2048, sums 4x256
#define SM_WIDE (184320 + 6144 + 1024)

template<int KPAD>
__global__ __launch_bounds__(512, 1)
void wide_mma_kernel(const __nv_bfloat16* __restrict__ Ahi,
                     const __nv_bfloat16* __restrict__ Alo,
                     const __nv_bfloat16* __restrict__ Whi,
                     const __nv_bfloat16* __restrict__ Wlo,
                     const float* __restrict__ bias,
                     const float* __restrict__ gamma,
                     const float* __restrict__ beta,
                     __nv_bfloat16* __restrict__ Ohi,
                     __nv_bfloat16* __restrict__ Olo)
{
    constexpr int NC = KPAD / 32;
    extern __shared__ char smem[];
    const uint32_t sb = smem_u32(smem);
    const int tid = threadIdx.x, lane = tid & 31, w = tid >> 5;
    const int warpM = w >> 3, warpN = w & 7;          // 2 x 8
    const int nbase = warpN * 64;
    const int tile = blockIdx.x;                      // 64-row tile

    float* sBias = (float*)(smem + SPAR);
    float* sG    = (float*)(smem + SPAR + 2048);
    float* sBe   = (float*)(smem + SPAR + 4096);
    float* sSum  = (float*)(smem + SPAR + 6144);
    float* sSum2 = (float*)(smem + SPAR + 6144 + 256);
    float* sMu   = (float*)(smem + SPAR + 6144 + 512);
    float* sRs   = (float*)(smem + SPAR + 6144 + 768);
    if (tid < 512) { sBias[tid] = bias[tid]; sG[tid] = gamma[tid]; sBe[tid] = beta[tid]; }
    if (tid < 64)  { sSum[tid] = 0.f; sSum2[tid] = 0.f; }

    // chunk loader: 64B of K per row, hi+lo, A(64 rows) + B^T(512 rows)
    auto load_chunk = [&](int c, int sel) {
        const int kbase = c * 32;
        const uint32_t bh = sb + SB_HI + sel * 40960;
        const uint32_t bl = sb + SB_LO + sel * 40960;
        for (int i = tid; i < 2048; i += 512) {
            int row = i >> 2, j = i & 3;
            size_t go = ((size_t)row * KPAD + kbase) * 2 + j * 16;
            cp16(bh + row * LDR + j * 16, (const char*)Whi + go);
            cp16(bl + row * LDR + j * 16, (const char*)Wlo + go);
        }
        const uint32_t ah = sb + SA_HI + sel * 5120;
        const uint32_t al = sb + SA_LO + sel * 5120;
        if (tid < 256) {
            int row = tid >> 2, j = tid & 3;
            size_t go = (((size_t)tile * 64 + row) * KPAD + kbase) * 2 + j * 16;
            cp16(ah + row * LDR + j * 16, (const char*)Ahi + go);
            cp16(al + row * LDR + j * 16, (const char*)Alo + go);
        }
        CP_COMMIT();
    };

    load_chunk(0, 0);
    if (NC > 1) load_chunk(1, 1);

    float acc[2][8][4];
#pragma unroll
    for (int i = 0; i < 2; i++)
#pragma unroll
        for (int j = 0; j < 8; j++)
#pragma unroll
            for (int r = 0; r < 4; r++) acc[i][j][r] = 0.f;

    // ldmatrix lane offsets
    const int arow = ((lane >> 3) & 1) * 8 + (lane & 7);
    const int acol = (lane >> 4) * 8;
    const int brow = ((lane >> 4) & 1) * 8 + (lane & 7);
    const int bcol = ((lane >> 3) & 1) * 8;

#pragma unroll 1
    for (int c = 0; c < NC; c++) {
        if (c + 1 < NC) CP_WAIT(1); else CP_WAIT(0);
        __syncthreads();
        const int sel = c & 1;
        const uint32_t bAh = sb + SA_HI + sel * 5120;
        const uint32_t bAl = sb + SA_LO + sel * 5120;
        const uint32_t bBh = sb + SB_HI + sel * 40960;
        const uint32_t bBl = sb + SB_LO + sel * 40960;
#pragma unroll
        for (int ks = 0; ks < 32; ks += 16) {
            uint32_t ah[2][4], al[2][4];
#pragma unroll
            for (int mf = 0; mf < 2; mf++) {
                const uint32_t ao = (uint32_t)((warpM * 32 + mf * 16 + arow) * LDR
                                               + (ks + acol) * 2);
                LDSM4(ah[mf][0], ah[mf][1], ah[mf][2], ah[mf][3], bAh + ao);
                LDSM4(al[mf][0], al[mf][1], al[mf][2], al[mf][3], bAl + ao);
            }
#pragma unroll
            for (int nq = 0; nq < 4; nq++) {
                const uint32_t bo = (uint32_t)((nbase + nq * 16 + brow) * LDR
                                               + (ks + bcol) * 2);
                uint32_t bh[4], bl[4];
                LDSM4(bh[0], bh[1], bh[2], bh[3], bBh + bo);
                LDSM4(bl[0], bl[1], bl[2], bl[3], bBl + bo);
#pragma unroll
                for (int mf = 0; mf < 2; mf++) {
                    float* d0 = acc[mf][nq * 2];
                    float* d1 = acc[mf][nq * 2 + 1];
                    MMA16816(d0, ah[mf], bh[0], bh[1]);
                    MMA16816(d0, ah[mf], bl[0], bl[1]);
                    MMA16816(d0, al[mf], bh[0], bh[1]);
                    MMA16816(d1, ah[mf], bh[2], bh[3]);
                    MMA16816(d1, ah[mf], bl[2], bl[3]);
                    MMA16816(d1, al[mf], bh[2], bh[3]);
                }
            }
        }
        __syncthreads();
        if (c + 2 < NC) load_chunk(c + 2, sel);
    }

    // ---------------- epilogue: bias + LN + SiLU + split bf16 store ---------
    // thread holds rows: warpM*32 + mf*16 + lane/4 + rh*8 ; cols nbase+idx*8+(lane&3)*2+{0,1}
#pragma unroll
    for (int mf = 0; mf < 2; mf++)
#pragma unroll
        for (int rh = 0; rh < 2; rh++) {
            float s = 0.f, s2 = 0.f;
#pragma unroll
            for (int idx = 0; idx < 8; idx++) {
                const int c0 = nbase + idx * 8 + (lane & 3) * 2;
                float v0 = acc[mf][idx][rh * 2]     + sBias[c0];
                float v1 = acc[mf][idx][rh * 2 + 1] + sBias[c0 + 1];
                acc[mf][idx][rh * 2] = v0; acc[mf][idx][rh * 2 + 1] = v1;
                s += v0 + v1; s2 += v0 * v0 + v1 * v1;
            }
            s  += __shfl_xor_sync(0xffffffffu, s, 1);
            s  += __shfl_xor_sync(0xffffffffu, s, 2);
            s2 += __shfl_xor_sync(0xffffffffu, s2, 1);
            s2 += __shfl_xor_sync(0xffffffffu, s2, 2);
            if ((lane & 3) == 0) {
                const int row = warpM * 32 + mf * 16 + (lane >> 2) + rh * 8;
                atomicAdd(&sSum[row], s);
                atomicAdd(&sSum2[row], s2);
            }
        }
    __syncthreads();
    if (tid < 64) {
        const float mu = sSum[tid] * (1.f / 512.f);
        const float var = sSum2[tid] * (1.f / 512.f) - mu * mu;
        sMu[tid] = mu; sRs[tid] = rsqrtf(var + 1e-5f);
    }
    __syncthreads();

#pragma unroll
    for (int mf = 0; mf < 2; mf++)
#pragma unroll
        for (int rh = 0; rh < 2; rh++) {
            const int row = warpM * 32 + mf * 16 + (lane >> 2) + rh * 8;
            const float mu = sMu[row], rs = sRs[row];
            const size_t rowg = (size_t)tile * 64 + row;
#pragma unroll
            for (int idx = 0; idx < 8; idx++) {
                const int c0 = nbase + idx * 8 + (lane & 3) * 2;
                float y0 = (acc[mf][idx][rh * 2]     - mu) * rs * sG[c0]     + sBe[c0];
                float y1 = (acc[mf][idx][rh * 2 + 1] - mu) * rs * sG[c0 + 1] + sBe[c0 + 1];
                y0 = y0 * (1.f / (1.f + __expf(-y0)));
                y1 = y1 * (1.f / (1.f + __expf(-y1)));
                const float h0 = __bfloat162float(__float2bfloat16(y0));
                const float h1 = __bfloat162float(__float2bfloat16(y1));
                *(uint32_t*)(Ohi + rowg * 512 + c0) = pack_bf2(h0, h1);
                *(uint32_t*)(Olo + rowg * 512 + c0) = pack_bf2(y0 - h0, y1 - h1);
            }
        }
}

// ============================================================================
// out layer: out[B,64] = A[B,512] @ W3 + b3 (fp32 out, no LN).
// CTA: M=128, N=64. 256 threads = 8 warps, grid 4(M) x 2(N), warp m32 x n32.
// ============================================================================
#define OA_HI 0                    // 2 x (128*80) = 20480
#define OA_LO 20480
#define OB_HI 40960                // 2 x (64*80)  = 10240
#define OB_LO 51200
#define SM_OUT 61440

__global__ __launch_bounds__(256, 1)
void out_mma_kernel(const __nv_bfloat16* __restrict__ Ahi,
                    const __nv_bfloat16* __restrict__ Alo,
                    const __nv_bfloat16* __restrict__ Whi,
                    const __nv_bfloat16* __restrict__ Wlo,
                    const float* __restrict__ bias,
                    float* __restrict__ out)
{
    constexpr int NC = 16;
    extern __shared__ char smem[];
    const uint32_t sb = smem_u32(smem);
    const int tid = threadIdx.x, lane = tid & 31, w = tid >> 5;
    const int warpM = w >> 1, warpN = w & 1;
    const int nbase = warpN * 32;
    const int tile = blockIdx.x;                      // 128-row tile

    auto load_chunk = [&](int c, int sel) {
        const int kbase = c * 32;
        const uint32_t bh = sb + OB_HI + sel * 5120;
        const uint32_t bl = sb + OB_LO + sel * 5120;
        if (tid < 256) {
            int row = tid >> 2, j = tid & 3;          // 64 rows x 4 quads
            size_t go = ((size_t)row * 512 + kbase) * 2 + j * 16;
            cp16(bh + row * LDR + j * 16, (const char*)Whi + go);
            cp16(bl + row * LDR + j * 16, (const char*)Wlo + go);
        }
        const uint32_t ah = sb + OA_HI + sel * 10240;
        const uint32_t al = sb + OA_LO + sel * 10240;
        for (int i = tid; i < 512; i += 256) {        // 128 rows x 4 quads
            int row = i >> 2, j = i & 3;
            size_t go = (((size_t)tile * 128 + row) * 512 + kbase) * 2 + j * 16;
            cp16(ah + row * LDR + j * 16, (const char*)Ahi + go);
            cp16(al + row * LDR + j * 16, (const char*)Alo + go);
        }
        CP_COMMIT();
    };

    load_chunk(0, 0);
    load_chunk(1, 1);

    float acc[2][4][4];
#pragma unroll
    for (int i = 0; i < 2; i++)
#pragma unroll
        for (int j = 0; j < 4; j++)
#pragma unroll
            for (int r = 0; r < 4; r++) acc[i][j][r] = 0.f;

    const int arow = ((lane >> 3) & 1) * 8 + (lane & 7);
    const int acol = (lane >> 4) * 8;
    const int brow = ((lane >> 4) & 1) * 8 + (lane & 7);
    const int bcol = ((lane >> 3) & 1) * 8;

#pragma unroll 1
    for (int c = 0; c < NC; c++) {
        if (c + 1 < NC) CP_WAIT(1); else CP_WAIT(0);
        __syncthreads();
        const int sel = c & 1;
        const uint32_t bAh = sb + OA_HI + sel * 10240;
        const uint32_t bAl = sb + OA_LO + sel * 10240;
        const uint32_t bBh = sb + OB_HI + sel * 5120;
        const uint32_t bBl = sb + OB_LO + sel * 5120;
#pragma unroll
        for (int ks = 0; ks < 32; ks += 16) {
            uint32_t ah[2][4], al[2][4];
#pragma unroll
            for (int mf = 0; mf < 2; mf++) {
                const uint32_t ao = (uint32_t)((warpM * 32 + mf * 16 + arow) * LDR
                                               + (ks + acol) * 2);
                LDSM4(ah[mf][0], ah[mf][1], ah[mf][2], ah[mf][3], bAh + ao);
                LDSM4(al[mf][0], al[mf][1], al[mf][2], al[mf][3], bAl + ao);
            }
#pragma unroll
            for (int nq = 0; nq < 2; nq++) {
                const uint32_t bo = (uint32_t)((nbase + nq * 16 + brow) * LDR
                                               + (ks + bcol) * 2);
                uint32_t bh[4], bl[4];
                LDSM4(bh[0], bh[1], bh[2], bh[3], bBh + bo);
                LDSM4(bl[0], bl[1], bl[2], bl[3], bBl + bo);
#pragma unroll
                for (int mf = 0; mf < 2; mf++) {
                    float* d0 = acc[mf][nq * 2];
                    float* d1 = acc[mf][nq * 2 + 1];
                    MMA16816(d0, ah[mf], bh[0], bh[1]);
                    MMA16816(d0, ah[mf], bl[0], bl[1]);
                    MMA16816(d0, al[mf], bh[0], bh[1]);
                    MMA16816(d1, ah[mf], bh[2], bh[3]);
                    MMA16816(d1, ah[mf], bl[2], bl[3]);
                    MMA16816(d1, al[mf], bh[2], bh[3]);
                }
            }
        }
        __syncthreads();
        if (c + 2 < NC) load_chunk(c + 2, sel);
    }

#pragma unroll
    for (int mf = 0; mf < 2; mf++)
#pragma unroll
        for (int rh = 0; rh < 2; rh++) {
            const int row = warpM * 32 + mf * 16 + (lane >> 2) + rh * 8;
            const size_t rowg = (size_t)tile * 128 + row;
#pragma unroll
            for (int idx = 0; idx < 4; idx++) {
                const int c0 = nbase + idx * 8 + (lane & 3) * 2;
                float2 o;
                o.x = acc[mf][idx][rh * 2]     + __ldg(bias + c0);
                o.y = acc[mf][idx][rh * 2 + 1] + __ldg(bias + c0 + 1);
                *(float2*)(out + rowg * 64 + c0) = o;
            }
        }
}

// ============================================================================
// enc3: z0[B,8] = tanh(h[B,512] @ W3[512,8] + b3), h from hi/lo row-major
// ============================================================================
__global__ __launch_bounds__(256, 4)
void enc3_kernel(const __nv_bfloat16* __restrict__ Hhi,
                 const __nv_bfloat16* __restrict__ Hlo,
                 const float* __restrict__ W3, const float* __restrict__ b3,
                 float* __restrict__ z0out)
{
    __shared__ float w[HID * LDIM];
    for (int i = threadIdx.x; i < HID * LDIM; i += 256) w[i] = W3[i];
    __syncthreads();

    const size_t row = (size_t)blockIdx.x * 256 + threadIdx.x;
    float z[8] = {0.f, 0.f, 0.f, 0.f, 0.f, 0.f, 0.f, 0.f};

    for (int k0 = 0; k0 < 512; k0 += 8) {
        uint4 qh = *(const uint4*)(Hhi + row * 512 + k0);
        uint4 ql = *(const uint4*)(Hlo + row * 512 + k0);
        const uint32_t hw[4] = {qh.x, qh.y, qh.z, qh.w};
        const uint32_t lw[4] = {ql.x, ql.y, ql.z, ql.w};
#pragma unroll
        for (int m = 0; m < 4; m++) {
            const float a0 = bf_lo(hw[m]) + bf_lo(lw[m]);
            const float a1 = bf_hi(hw[m]) + bf_hi(lw[m]);
            const float* w0 = w + (k0 + m * 2) * 8;
#pragma unroll
            for (int j = 0; j < 8; j++) {
                z[j] = fmaf(a0, w0[j], z[j]);
                z[j] = fmaf(a1, w0[8 + j], z[j]);
            }
        }
    }
#pragma unroll
    for (int j = 0; j < 8; j++)
        z0out[row * 8 + j] = tanhf(z[j] + __ldg(b3 + j));
}

// ============================================================================
// integrator: 20 Euler steps; outputs split bf16 row-major padded to 32 cols
// ============================================================================
__global__ __launch_bounds__(256, 4)
void integrate_kernel(const float* __restrict__ z0,
                      const float* __restrict__ dtv,
                      const float* __restrict__ Xi,
                      __nv_bfloat16* __restrict__ Zhi,
                      __nv_bfloat16* __restrict__ Zlo)
{
    __shared__ float Xis[NTH * LDIM];
    for (int i = threadIdx.x; i < NTH * LDIM; i += 256) Xis[i] = Xi[i];
    __syncthreads();

    const size_t row = (size_t)blockIdx.x * 256 + threadIdx.x;
    float z[8];
    *(float4*)&z[0] = *(const float4*)(z0 + row * 8);
    *(float4*)&z[4] = *(const float4*)(z0 + row * 8 + 4);
    const float dt = dtv[row] * (1.f / (float)NSTEPS);

#pragma unroll 1
    for (int s = 0; s < NSTEPS; s++) {
        float zd[8];
#pragma unroll
        for (int j = 0; j < 8; j++) zd[j] = Xis[j];
#pragma unroll
        for (int i = 0; i < 8; i++) {
            const float t = z[i];
#pragma unroll
            for (int j = 0; j < 8; j++)
                zd[j] = fmaf(t, Xis[(1 + i) * 8 + j], zd[j]);
        }
        int idx = 9;
#pragma unroll
        for (int i = 0; i < 8; i++)
#pragma unroll
            for (int k = i; k < 8; k++) {
                const float q = z[i] * z[k];
#pragma unroll
                for (int j = 0; j < 8; j++)
                    zd[j] = fmaf(q, Xis[idx * 8 + j], zd[j]);
                idx++;
            }
#pragma unroll
        for (int j = 0; j < 8; j++) z[j] = fmaf(zd[j], dt, z[j]);
    }

    float h[8];
#pragma unroll
    for (int e = 0; e < 8; e++) h[e] = __bfloat162float(__float2bfloat16(z[e]));
    uint4 qh, ql, qz;
    qh.x = pack_bf2(h[0], h[1]); qh.y = pack_bf2(h[2], h[3]);
    qh.z = pack_bf2(h[4], h[5]); qh.w = pack_bf2(h[6], h[7]);
    ql.x = pack_bf2(z[0] - h[0], z[1] - h[1]); ql.y = pack_bf2(z[2] - h[2], z[3] - h[3]);
    ql.z = pack_bf2(z[4] - h[4], z[5] - h[5]); ql.w = pack_bf2(z[6] - h[6], z[7] - h[7]);
    qz.x = qz.y = qz.z = qz.w = 0u;
    uint4* ph = (uint4*)(Zhi + row * 32);
    uint4* pl = (uint4*)(Zlo + row * 32);
    ph[0] = qh; ph[1] = qz; ph[2] = qz; ph[3] = qz;
    pl[0] = ql; pl[1] = qz; pl[2] = qz; pl[3] = qz;
}

// ============================================================================
extern "C" void kernel_launch(void* const* d_in, const int* in_sizes, int n_in,
                              void* d_out, int out_size)
{
    (void)in_sizes; (void)n_in; (void)out_size;
    const float* x0   = (const float*)d_in[0];
    const float* dtn  = (const float*)d_in[1];
    const float* eW1  = (const float*)d_in[4];
    const float* eb1  = (const float*)d_in[5];
    const float* eg1  = (const float*)d_in[6];
    const float* ebe1 = (const float*)d_in[7];
    const float* eW2  = (const float*)d_in[8];
    const float* eb2  = (const float*)d_in[9];
    const float* eg2  = (const float*)d_in[10];
    const float* ebe2 = (const float*)d_in[11];
    const float* eW3  = (const float*)d_in[12];
    const float* eb3  = (const float*)d_in[13];
    const float* dW1  = (const float*)d_in[14];
    const float* db1  = (const float*)d_in[15];
    const float* dg1  = (const float*)d_in[16];
    const float* dbe1 = (const float*)d_in[17];
    const float* dW2  = (const float*)d_in[18];
    const float* db2  = (const float*)d_in[19];
    const float* dg2  = (const float*)d_in[20];
    const float* dbe2 = (const float*)d_in[21];
    const float* dW3  = (const float*)d_in[22];
    const float* db3  = (const float*)d_in[23];
    const float* Xi   = (const float*)d_in[24];
    float* out = (float*)d_out;

    __nv_bfloat16 *hAh, *hAl, *hBh, *hBl, *xh, *xl, *zh, *zl;
    __nv_bfloat16 *w1h, *w1l, *w2h, *w2l, *d1h, *d1l, *d2h, *d2l, *d3h, *d3l;
    float* z0;
    cudaGetSymbolAddress((void**)&hAh, g_hA_hi); cudaGetSymbolAddress((void**)&hAl, g_hA_lo);
    cudaGetSymbolAddress((void**)&hBh, g_hB_hi); cudaGetSymbolAddress((void**)&hBl, g_hB_lo);
    cudaGetSymbolAddress((void**)&xh,  g_x_hi);  cudaGetSymbolAddress((void**)&xl,  g_x_lo);
    cudaGetSymbolAddress((void**)&zh,  g_z_hi);  cudaGetSymbolAddress((void**)&zl,  g_z_lo);
    cudaGetSymbolAddress((void**)&z0,  g_z0);
    cudaGetSymbolAddress((void**)&w1h, g_w1_hi); cudaGetSymbolAddress((void**)&w1l, g_w1_lo);
    cudaGetSymbolAddress((void**)&w2h, g_w2_hi); cudaGetSymbolAddress((void**)&w2l, g_w2_lo);
    cudaGetSymbolAddress((void**)&d1h, g_d1_hi); cudaGetSymbolAddress((void**)&d1l, g_d1_lo);
    cudaGetSymbolAddress((void**)&d2h, g_d2_hi); cudaGetSymbolAddress((void**)&d2l, g_d2_lo);
    cudaGetSymbolAddress((void**)&d3h, g_d3_hi); cudaGetSymbolAddress((void**)&d3l, g_d3_lo);

    cudaFuncSetAttribute(wide_mma_kernel<64>,
        cudaFuncAttributeMaxDynamicSharedMemorySize, SM_WIDE);
    cudaFuncSetAttribute(wide_mma_kernel<32>,
        cudaFuncAttributeMaxDynamicSharedMemorySize, SM_WIDE);
    cudaFuncSetAttribute(wide_mma_kernel<512>,
        cudaFuncAttributeMaxDynamicSharedMemorySize, SM_WIDE);
    cudaFuncSetAttribute(out_mma_kernel,
        cudaFuncAttributeMaxDynamicSharedMemorySize, SM_OUT);

    // ---- prep (weights transposed+split, input split) ----
    prep_wT_kernel<<<(512 * 64 + 255) / 256, 256>>>(eW1, 64, 512, 64, 512 * 64, w1h, w1l);
    prep_wT_kernel<<<(512 * 512 + 255) / 256, 256>>>(eW2, 512, 512, 512, 512 * 512, w2h, w2l);
    prep_wT_kernel<<<(512 * 32 + 255) / 256, 256>>>(dW1, 8, 512, 32, 512 * 32, d1h, d1l);
    prep_wT_kernel<<<(512 * 512 + 255) / 256, 256>>>(dW2, 512, 512, 512, 512 * 512, d2h, d2l);
    prep_wT_kernel<<<(64 * 512 + 255) / 256, 256>>>(dW3, 512, 64, 512, 64 * 512, d3h, d3l);
    prep_x_kernel<<<(BATCH * 64) / 256, 256>>>(x0, xh, xl);

    const int nwide = BATCH / 64;    // 2048

    // ---- pipeline ----
    wide_mma_kernel<64><<<nwide, 512, SM_WIDE>>>(
        xh, xl, w1h, w1l, eb1, eg1, ebe1, hAh, hAl);
    wide_mma_kernel<512><<<nwide, 512, SM_WIDE>>>(
        hAh, hAl, w2h, w2l, eb2, eg2, ebe2, hBh, hBl);
    enc3_kernel<<<BATCH / 256, 256>>>(hBh, hBl, eW3, eb3, z0);
    integrate_kernel<<<BATCH / 256, 256>>>(z0, dtn, Xi, zh, zl);
    wide_mma_kernel<32><<<nwide, 512, SM_WIDE>>>(
        zh, zl, d1h, d1l, db1, dg1, dbe1, hAh, hAl);
    wide_mma_kernel<512><<<nwide, 512, SM_WIDE>>>(
        hAh, hAl, d2h, d2l, db2, dg2, dbe2, hBh, hBl);
    out_mma_kernel<<<BATCH / 128, 256, SM_OUT>>>(hBh, hBl, d3h, d3l, db3, out);
}

// round 6
// speedup vs baseline: 1.7968x; 1.0014x over previous
#include <cuda_runtime.h>
#include <cuda_bf16.h>
#include <math.h>
#include <stdint.h>

#define BATCH   131072
#define HID     512
#define LDIM    8
#define NTH     45
#define NSTEPS  20

// ============================================================================
// Baseline-PTX tensor helpers (compute_103-safe: ldmatrix + mma.sync only)
// ============================================================================
__device__ __forceinline__ uint32_t smem_u32(const void* p) {
    uint32_t a;
    asm("{ .reg .u64 t; cvta.to.shared.u64 t, %1; cvt.u32.u64 %0, t; }"
        : "=r"(a) : "l"(p));
    return a;
}

#define LDSM4(r0, r1, r2, r3, addr) \
    asm volatile("ldmatrix.sync.aligned.m8n8.x4.shared.b16 {%0,%1,%2,%3}, [%4];" \
        : "=r"(r0), "=r"(r1), "=r"(r2), "=r"(r3) : "r"(addr))

#define MMA16816(d, a, b0, b1) \
    asm volatile("mma.sync.aligned.m16n8k16.row.col.f32.bf16.bf16.f32 " \
        "{%0,%1,%2,%3},{%4,%5,%6,%7},{%8,%9},{%0,%1,%2,%3};" \
        : "+f"((d)[0]), "+f"((d)[1]), "+f"((d)[2]), "+f"((d)[3]) \
        : "r"((a)[0]), "r"((a)[1]), "r"((a)[2]), "r"((a)[3]), \
          "r"(b0), "r"(b1))

__device__ __forceinline__ void cp16(uint32_t dst, const void* src) {
    asm volatile("cp.async.cg.shared.global [%0], [%1], 16;"
        :: "r"(dst), "l"(src));
}
#define CP_COMMIT() asm volatile("cp.async.commit_group;" ::: "memory")
#define CP_WAIT(n)  asm volatile("cp.async.wait_group %0;" :: "n"(n) : "memory")

__device__ __forceinline__ uint32_t pack_bf2(float a, float b) {
    __nv_bfloat162 t = __floats2bfloat162_rn(a, b);
    return reinterpret_cast<uint32_t&>(t);
}
__device__ __forceinline__ float bf_lo(uint32_t u) {
    return __bfloat162float(__ushort_as_bfloat16((unsigned short)(u & 0xffffu)));
}
__device__ __forceinline__ float bf_hi(uint32_t u) {
    return __bfloat162float(__ushort_as_bfloat16((unsigned short)(u >> 16)));
}

// ============================================================================
// Scratch (allocation-free rule): activations as row-major bf16 hi/lo pairs.
// ============================================================================
__device__ __nv_bfloat16 g_hA_hi[BATCH * HID], g_hA_lo[BATCH * HID];
__device__ __nv_bfloat16 g_hB_hi[BATCH * HID], g_hB_lo[BATCH * HID];
__device__ __nv_bfloat16 g_x_hi[BATCH * 64],   g_x_lo[BATCH * 64];
__device__ __nv_bfloat16 g_z_hi[BATCH * 32],   g_z_lo[BATCH * 32];  // zt pad 32
__device__ float         g_z0[BATCH * LDIM];

// Weights pre-transposed WT[n][kpad] (row-major), split hi/lo, zero-pad k>=K
__device__ __nv_bfloat16 g_w1_hi[512 * 64],  g_w1_lo[512 * 64];    // enc_W1
__device__ __nv_bfloat16 g_w2_hi[512 * 512], g_w2_lo[512 * 512];   // enc_W2
__device__ __nv_bfloat16 g_d1_hi[512 * 32],  g_d1_lo[512 * 32];    // dec_W1 (K=8 pad 32)
__device__ __nv_bfloat16 g_d2_hi[512 * 512], g_d2_lo[512 * 512];   // dec_W2
__device__ __nv_bfloat16 g_d3_hi[64 * 512],  g_d3_lo[64 * 512];    // dec_W3

// ============================================================================
// prep kernels
// ============================================================================
__global__ void prep_wT_kernel(const float* __restrict__ W, int K, int N, int KPAD,
                               int total, __nv_bfloat16* __restrict__ hi,
                               __nv_bfloat16* __restrict__ lo)
{
    int idx = blockIdx.x * 256 + threadIdx.x;
    if (idx >= total) return;
    int n = idx / KPAD, k = idx % KPAD;
    float v = (k < K) ? W[(size_t)k * N + n] : 0.f;
    float h = __bfloat162float(__float2bfloat16(v));
    hi[idx] = __float2bfloat16(h);
    lo[idx] = __float2bfloat16(v - h);
}

__global__ void prep_x_kernel(const float* __restrict__ x0,
                              __nv_bfloat16* __restrict__ hi,
                              __nv_bfloat16* __restrict__ lo)
{
    size_t idx = (size_t)blockIdx.x * 256 + threadIdx.x;
    float v = x0[idx];
    float h = __bfloat162float(__float2bfloat16(v));
    hi[idx] = __float2bfloat16(h);
    lo[idx] = __float2bfloat16(v - h);
}

// ============================================================================
// wide layer: O[B,512] = SiLU(LN(A[B,KPAD] @ W + b)), bf16x3 split MMA.
// CTA: M=64 rows, N=512 (full row -> fused LN). 512 threads = 16 warps,
// warp grid 2(M) x 8(N), warp tile m32 x n64. BK=32, cp.async double buffer.
// smem rows padded to 80B -> conflict-free ldmatrix.
// ============================================================================
#define LDR 80                     // padded smem row bytes (40 bf16)
#define SA_HI 0                    // 2 x (64*80)   = 10240
#define SA_LO 10240                // 2 x (64*80)   = 10240
#define SB_HI 20480                // 2 x (512*80)  = 81920
#define SB_LO 102400               // 2 x (512*80)  = 81920
#define SPAR  184320               // bias/g/beta 3x2048, sums 4x256
#define SM_WIDE (184320 + 6144 + 1024)

template<int KPAD>
__global__ __launch_bounds__(512, 1)
void wide_mma_kernel(const __nv_bfloat16* __restrict__ Ahi,
                     const __nv_bfloat16* __restrict__ Alo,
                     const __nv_bfloat16* __restrict__ Whi,
                     const __nv_bfloat16* __restrict__ Wlo,
                     const float* __restrict__ bias,
                     const float* __restrict__ gamma,
                     const float* __restrict__ beta,
                     __nv_bfloat16* __restrict__ Ohi,
                     __nv_bfloat16* __restrict__ Olo)
{
    constexpr int NC = KPAD / 32;
    extern __shared__ char smem[];
    const uint32_t sb = smem_u32(smem);
    const int tid = threadIdx.x, lane = tid & 31, w = tid >> 5;
    const int warpM = w >> 3, warpN = w & 7;          // 2 x 8
    const int nbase = warpN * 64;
    const int tile = blockIdx.x;                      // 64-row tile

    float* sBias = (float*)(smem + SPAR);
    float* sG    = (float*)(smem + SPAR + 2048);
    float* sBe   = (float*)(smem + SPAR + 4096);
    float* sSum  = (float*)(smem + SPAR + 6144);
    float* sSum2 = (float*)(smem + SPAR + 6144 + 256);
    float* sMu   = (float*)(smem + SPAR + 6144 + 512);
    float* sRs   = (float*)(smem + SPAR + 6144 + 768);
    if (tid < 512) { sBias[tid] = bias[tid]; sG[tid] = gamma[tid]; sBe[tid] = beta[tid]; }
    if (tid < 64)  { sSum[tid] = 0.f; sSum2[tid] = 0.f; }

    // chunk loader: 64B of K per row, hi+lo, A(64 rows) + B^T(512 rows)
    auto load_chunk = [&](int c, int sel) {
        const int kbase = c * 32;
        const uint32_t bh = sb + SB_HI + sel * 40960;
        const uint32_t bl = sb + SB_LO + sel * 40960;
        for (int i = tid; i < 2048; i += 512) {
            int row = i >> 2, j = i & 3;
            size_t go = ((size_t)row * KPAD + kbase) * 2 + j * 16;
            cp16(bh + row * LDR + j * 16, (const char*)Whi + go);
            cp16(bl + row * LDR + j * 16, (const char*)Wlo + go);
        }
        const uint32_t ah = sb + SA_HI + sel * 5120;
        const uint32_t al = sb + SA_LO + sel * 5120;
        if (tid < 256) {
            int row = tid >> 2, j = tid & 3;
            size_t go = (((size_t)tile * 64 + row) * KPAD + kbase) * 2 + j * 16;
            cp16(ah + row * LDR + j * 16, (const char*)Ahi + go);
            cp16(al + row * LDR + j * 16, (const char*)Alo + go);
        }
        CP_COMMIT();
    };

    load_chunk(0, 0);
    if (NC > 1) load_chunk(1, 1);

    float acc[2][8][4];
#pragma unroll
    for (int i = 0; i < 2; i++)
#pragma unroll
        for (int j = 0; j < 8; j++)
#pragma unroll
            for (int r = 0; r < 4; r++) acc[i][j][r] = 0.f;

    // ldmatrix lane offsets
    const int arow = ((lane >> 3) & 1) * 8 + (lane & 7);
    const int acol = (lane >> 4) * 8;
    const int brow = ((lane >> 4) & 1) * 8 + (lane & 7);
    const int bcol = ((lane >> 3) & 1) * 8;

#pragma unroll 1
    for (int c = 0; c < NC; c++) {
        if (c + 1 < NC) CP_WAIT(1); else CP_WAIT(0);
        __syncthreads();
        const int sel = c & 1;
        const uint32_t bAh = sb + SA_HI + sel * 5120;
        const uint32_t bAl = sb + SA_LO + sel * 5120;
        const uint32_t bBh = sb + SB_HI + sel * 40960;
        const uint32_t bBl = sb + SB_LO + sel * 40960;
#pragma unroll
        for (int ks = 0; ks < 32; ks += 16) {
            uint32_t ah[2][4], al[2][4];
#pragma unroll
            for (int mf = 0; mf < 2; mf++) {
                const uint32_t ao = (uint32_t)((warpM * 32 + mf * 16 + arow) * LDR
                                               + (ks + acol) * 2);
                LDSM4(ah[mf][0], ah[mf][1], ah[mf][2], ah[mf][3], bAh + ao);
                LDSM4(al[mf][0], al[mf][1], al[mf][2], al[mf][3], bAl + ao);
            }
#pragma unroll
            for (int nq = 0; nq < 4; nq++) {
                const uint32_t bo = (uint32_t)((nbase + nq * 16 + brow) * LDR
                                               + (ks + bcol) * 2);
                uint32_t bh[4], bl[4];
                LDSM4(bh[0], bh[1], bh[2], bh[3], bBh + bo);
                LDSM4(bl[0], bl[1], bl[2], bl[3], bBl + bo);
#pragma unroll
                for (int mf = 0; mf < 2; mf++) {
                    float* d0 = acc[mf][nq * 2];
                    float* d1 = acc[mf][nq * 2 + 1];
                    MMA16816(d0, ah[mf], bh[0], bh[1]);
                    MMA16816(d0, ah[mf], bl[0], bl[1]);
                    MMA16816(d0, al[mf], bh[0], bh[1]);
                    MMA16816(d1, ah[mf], bh[2], bh[3]);
                    MMA16816(d1, ah[mf], bl[2], bl[3]);
                    MMA16816(d1, al[mf], bh[2], bh[3]);
                }
            }
        }
        __syncthreads();
        if (c + 2 < NC) load_chunk(c + 2, sel);
    }

    // ---------------- epilogue: bias + LN + SiLU + split bf16 store ---------
    // thread holds rows: warpM*32 + mf*16 + lane/4 + rh*8 ; cols nbase+idx*8+(lane&3)*2+{0,1}
#pragma unroll
    for (int mf = 0; mf < 2; mf++)
#pragma unroll
        for (int rh = 0; rh < 2; rh++) {
            float s = 0.f, s2 = 0.f;
#pragma unroll
            for (int idx = 0; idx < 8; idx++) {
                const int c0 = nbase + idx * 8 + (lane & 3) * 2;
                float v0 = acc[mf][idx][rh * 2]     + sBias[c0];
                float v1 = acc[mf][idx][rh * 2 + 1] + sBias[c0 + 1];
                acc[mf][idx][rh * 2] = v0; acc[mf][idx][rh * 2 + 1] = v1;
                s += v0 + v1; s2 += v0 * v0 + v1 * v1;
            }
            s  += __shfl_xor_sync(0xffffffffu, s, 1);
            s  += __shfl_xor_sync(0xffffffffu, s, 2);
            s2 += __shfl_xor_sync(0xffffffffu, s2, 1);
            s2 += __shfl_xor_sync(0xffffffffu, s2, 2);
            if ((lane & 3) == 0) {
                const int row = warpM * 32 + mf * 16 + (lane >> 2) + rh * 8;
                atomicAdd(&sSum[row], s);
                atomicAdd(&sSum2[row], s2);
            }
        }
    __syncthreads();
    if (tid < 64) {
        const float mu = sSum[tid] * (1.f / 512.f);
        const float var = sSum2[tid] * (1.f / 512.f) - mu * mu;
        sMu[tid] = mu; sRs[tid] = rsqrtf(var + 1e-5f);
    }
    __syncthreads();

#pragma unroll
    for (int mf = 0; mf < 2; mf++)
#pragma unroll
        for (int rh = 0; rh < 2; rh++) {
            const int row = warpM * 32 + mf * 16 + (lane >> 2) + rh * 8;
            const float mu = sMu[row], rs = sRs[row];
            const size_t rowg = (size_t)tile * 64 + row;
#pragma unroll
            for (int idx = 0; idx < 8; idx++) {
                const int c0 = nbase + idx * 8 + (lane & 3) * 2;
                float y0 = (acc[mf][idx][rh * 2]     - mu) * rs * sG[c0]     + sBe[c0];
                float y1 = (acc[mf][idx][rh * 2 + 1] - mu) * rs * sG[c0 + 1] + sBe[c0 + 1];
                y0 = y0 * (1.f / (1.f + __expf(-y0)));
                y1 = y1 * (1.f / (1.f + __expf(-y1)));
                const float h0 = __bfloat162float(__float2bfloat16(y0));
                const float h1 = __bfloat162float(__float2bfloat16(y1));
                *(uint32_t*)(Ohi + rowg * 512 + c0) = pack_bf2(h0, h1);
                *(uint32_t*)(Olo + rowg * 512 + c0) = pack_bf2(y0 - h0, y1 - h1);
            }
        }
}

// ============================================================================
// out layer: out[B,64] = A[B,512] @ W3 + b3 (fp32 out, no LN).
// CTA: M=128, N=64. 256 threads = 8 warps, grid 4(M) x 2(N), warp m32 x n32.
// ============================================================================
#define OA_HI 0                    // 2 x (128*80) = 20480
#define OA_LO 20480
#define OB_HI 40960                // 2 x (64*80)  = 10240
#define OB_LO 51200
#define SM_OUT 61440

__global__ __launch_bounds__(256, 1)
void out_mma_kernel(const __nv_bfloat16* __restrict__ Ahi,
                    const __nv_bfloat16* __restrict__ Alo,
                    const __nv_bfloat16* __restrict__ Whi,
                    const __nv_bfloat16* __restrict__ Wlo,
                    const float* __restrict__ bias,
                    float* __restrict__ out)
{
    constexpr int NC = 16;
    extern __shared__ char smem[];
    const uint32_t sb = smem_u32(smem);
    const int tid = threadIdx.x, lane = tid & 31, w = tid >> 5;
    const int warpM = w >> 1, warpN = w & 1;
    const int nbase = warpN * 32;
    const int tile = blockIdx.x;                      // 128-row tile

    auto load_chunk = [&](int c, int sel) {
        const int kbase = c * 32;
        const uint32_t bh = sb + OB_HI + sel * 5120;
        const uint32_t bl = sb + OB_LO + sel * 5120;
        if (tid < 256) {
            int row = tid >> 2, j = tid & 3;          // 64 rows x 4 quads
            size_t go = ((size_t)row * 512 + kbase) * 2 + j * 16;
            cp16(bh + row * LDR + j * 16, (const char*)Whi + go);
            cp16(bl + row * LDR + j * 16, (const char*)Wlo + go);
        }
        const uint32_t ah = sb + OA_HI + sel * 10240;
        const uint32_t al = sb + OA_LO + sel * 10240;
        for (int i = tid; i < 512; i += 256) {        // 128 rows x 4 quads
            int row = i >> 2, j = i & 3;
            size_t go = (((size_t)tile * 128 + row) * 512 + kbase) * 2 + j * 16;
            cp16(ah + row * LDR + j * 16, (const char*)Ahi + go);
            cp16(al + row * LDR + j * 16, (const char*)Alo + go);
        }
        CP_COMMIT();
    };

    load_chunk(0, 0);
    load_chunk(1, 1);

    float acc[2][4][4];
#pragma unroll
    for (int i = 0; i < 2; i++)
#pragma unroll
        for (int j = 0; j < 4; j++)
#pragma unroll
            for (int r = 0; r < 4; r++) acc[i][j][r] = 0.f;

    const int arow = ((lane >> 3) & 1) * 8 + (lane & 7);
    const int acol = (lane >> 4) * 8;
    const int brow = ((lane >> 4) & 1) * 8 + (lane & 7);
    const int bcol = ((lane >> 3) & 1) * 8;

#pragma unroll 1
    for (int c = 0; c < NC; c++) {
        if (c + 1 < NC) CP_WAIT(1); else CP_WAIT(0);
        __syncthreads();
        const int sel = c & 1;
        const uint32_t bAh = sb + OA_HI + sel * 10240;
        const uint32_t bAl = sb + OA_LO + sel * 10240;
        const uint32_t bBh = sb + OB_HI + sel * 5120;
        const uint32_t bBl = sb + OB_LO + sel * 5120;
#pragma unroll
        for (int ks = 0; ks < 32; ks += 16) {
            uint32_t ah[2][4], al[2][4];
#pragma unroll
            for (int mf = 0; mf < 2; mf++) {
                const uint32_t ao = (uint32_t)((warpM * 32 + mf * 16 + arow) * LDR
                                               + (ks + acol) * 2);
                LDSM4(ah[mf][0], ah[mf][1], ah[mf][2], ah[mf][3], bAh + ao);
                LDSM4(al[mf][0], al[mf][1], al[mf][2], al[mf][3], bAl + ao);
            }
#pragma unroll
            for (int nq = 0; nq < 2; nq++) {
                const uint32_t bo = (uint32_t)((nbase + nq * 16 + brow) * LDR
                                               + (ks + bcol) * 2);
                uint32_t bh[4], bl[4];
                LDSM4(bh[0], bh[1], bh[2], bh[3], bBh + bo);
                LDSM4(bl[0], bl[1], bl[2], bl[3], bBl + bo);
#pragma unroll
                for (int mf = 0; mf < 2; mf++) {
                    float* d0 = acc[mf][nq * 2];
                    float* d1 = acc[mf][nq * 2 + 1];
                    MMA16816(d0, ah[mf], bh[0], bh[1]);
                    MMA16816(d0, ah[mf], bl[0], bl[1]);
                    MMA16816(d0, al[mf], bh[0], bh[1]);
                    MMA16816(d1, ah[mf], bh[2], bh[3]);
                    MMA16816(d1, ah[mf], bl[2], bl[3]);
                    MMA16816(d1, al[mf], bh[2], bh[3]);
                }
            }
        }
        __syncthreads();
        if (c + 2 < NC) load_chunk(c + 2, sel);
    }

#pragma unroll
    for (int mf = 0; mf < 2; mf++)
#pragma unroll
        for (int rh = 0; rh < 2; rh++) {
            const int row = warpM * 32 + mf * 16 + (lane >> 2) + rh * 8;
            const size_t rowg = (size_t)tile * 128 + row;
#pragma unroll
            for (int idx = 0; idx < 4; idx++) {
                const int c0 = nbase + idx * 8 + (lane & 3) * 2;
                float2 o;
                o.x = acc[mf][idx][rh * 2]     + __ldg(bias + c0);
                o.y = acc[mf][idx][rh * 2 + 1] + __ldg(bias + c0 + 1);
                *(float2*)(out + rowg * 64 + c0) = o;
            }
        }
}

// ============================================================================
// enc3: z0[B,8] = tanh(h[B,512] @ W3[512,8] + b3), h from hi/lo row-major
// ============================================================================
__global__ __launch_bounds__(256, 4)
void enc3_kernel(const __nv_bfloat16* __restrict__ Hhi,
                 const __nv_bfloat16* __restrict__ Hlo,
                 const float* __restrict__ W3, const float* __restrict__ b3,
                 float* __restrict__ z0out)
{
    __shared__ float w[HID * LDIM];
    for (int i = threadIdx.x; i < HID * LDIM; i += 256) w[i] = W3[i];
    __syncthreads();

    const size_t row = (size_t)blockIdx.x * 256 + threadIdx.x;
    float z[8] = {0.f, 0.f, 0.f, 0.f, 0.f, 0.f, 0.f, 0.f};

    for (int k0 = 0; k0 < 512; k0 += 8) {
        uint4 qh = *(const uint4*)(Hhi + row * 512 + k0);
        uint4 ql = *(const uint4*)(Hlo + row * 512 + k0);
        const uint32_t hw[4] = {qh.x, qh.y, qh.z, qh.w};
        const uint32_t lw[4] = {ql.x, ql.y, ql.z, ql.w};
#pragma unroll
        for (int m = 0; m < 4; m++) {
            const float a0 = bf_lo(hw[m]) + bf_lo(lw[m]);
            const float a1 = bf_hi(hw[m]) + bf_hi(lw[m]);
            const float* w0 = w + (k0 + m * 2) * 8;
#pragma unroll
            for (int j = 0; j < 8; j++) {
                z[j] = fmaf(a0, w0[j], z[j]);
                z[j] = fmaf(a1, w0[8 + j], z[j]);
            }
        }
    }
#pragma unroll
    for (int j = 0; j < 8; j++)
        z0out[row * 8 + j] = tanhf(z[j] + __ldg(b3 + j));
}

// ============================================================================
// integrator: 20 Euler steps; outputs split bf16 row-major padded to 32 cols
// ============================================================================
__global__ __launch_bounds__(256, 4)
void integrate_kernel(const float* __restrict__ z0,
                      const float* __restrict__ dtv,
                      const float* __restrict__ Xi,
                      __nv_bfloat16* __restrict__ Zhi,
                      __nv_bfloat16* __restrict__ Zlo)
{
    __shared__ float Xis[NTH * LDIM];
    for (int i = threadIdx.x; i < NTH * LDIM; i += 256) Xis[i] = Xi[i];
    __syncthreads();

    const size_t row = (size_t)blockIdx.x * 256 + threadIdx.x;
    float z[8];
    *(float4*)&z[0] = *(const float4*)(z0 + row * 8);
    *(float4*)&z[4] = *(const float4*)(z0 + row * 8 + 4);
    const float dt = dtv[row] * (1.f / (float)NSTEPS);

#pragma unroll 1
    for (int s = 0; s < NSTEPS; s++) {
        float zd[8];
#pragma unroll
        for (int j = 0; j < 8; j++) zd[j] = Xis[j];
#pragma unroll
        for (int i = 0; i < 8; i++) {
            const float t = z[i];
#pragma unroll
            for (int j = 0; j < 8; j++)
                zd[j] = fmaf(t, Xis[(1 + i) * 8 + j], zd[j]);
        }
        int idx = 9;
#pragma unroll
        for (int i = 0; i < 8; i++)
#pragma unroll
            for (int k = i; k < 8; k++) {
                const float q = z[i] * z[k];
#pragma unroll
                for (int j = 0; j < 8; j++)
                    zd[j] = fmaf(q, Xis[idx * 8 + j], zd[j]);
                idx++;
            }
#pragma unroll
        for (int j = 0; j < 8; j++) z[j] = fmaf(zd[j], dt, z[j]);
    }

    float h[8];
#pragma unroll
    for (int e = 0; e < 8; e++) h[e] = __bfloat162float(__float2bfloat16(z[e]));
    uint4 qh, ql, qz;
    qh.x = pack_bf2(h[0], h[1]); qh.y = pack_bf2(h[2], h[3]);
    qh.z = pack_bf2(h[4], h[5]); qh.w = pack_bf2(h[6], h[7]);
    ql.x = pack_bf2(z[0] - h[0], z[1] - h[1]); ql.y = pack_bf2(z[2] - h[2], z[3] - h[3]);
    ql.z = pack_bf2(z[4] - h[4], z[5] - h[5]); ql.w = pack_bf2(z[6] - h[6], z[7] - h[7]);
    qz.x = qz.y = qz.z = qz.w = 0u;
    uint4* ph = (uint4*)(Zhi + row * 32);
    uint4* pl = (uint4*)(Zlo + row * 32);
    ph[0] = qh; ph[1] = qz; ph[2] = qz; ph[3] = qz;
    pl[0] = ql; pl[1] = qz; pl[2] = qz; pl[3] = qz;
}

// ============================================================================
extern "C" void kernel_launch(void* const* d_in, const int* in_sizes, int n_in,
                              void* d_out, int out_size)
{
    (void)in_sizes; (void)n_in; (void)out_size;
    const float* x0   = (const float*)d_in[0];
    const float* dtn  = (const float*)d_in[1];
    const float* eW1  = (const float*)d_in[4];
    const float* eb1  = (const float*)d_in[5];
    const float* eg1  = (const float*)d_in[6];
    const float* ebe1 = (const float*)d_in[7];
    const float* eW2  = (const float*)d_in[8];
    const float* eb2  = (const float*)d_in[9];
    const float* eg2  = (const float*)d_in[10];
    const float* ebe2 = (const float*)d_in[11];
    const float* eW3  = (const float*)d_in[12];
    const float* eb3  = (const float*)d_in[13];
    const float* dW1  = (const float*)d_in[14];
    const float* db1  = (const float*)d_in[15];
    const float* dg1  = (const float*)d_in[16];
    const float* dbe1 = (const float*)d_in[17];
    const float* dW2  = (const float*)d_in[18];
    const float* db2  = (const float*)d_in[19];
    const float* dg2  = (const float*)d_in[20];
    const float* dbe2 = (const float*)d_in[21];
    const float* dW3  = (const float*)d_in[22];
    const float* db3  = (const float*)d_in[23];
    const float* Xi   = (const float*)d_in[24];
    float* out = (float*)d_out;

    __nv_bfloat16 *hAh, *hAl, *hBh, *hBl, *xh, *xl, *zh, *zl;
    __nv_bfloat16 *w1h, *w1l, *w2h, *w2l, *d1h, *d1l, *d2h, *d2l, *d3h, *d3l;
    float* z0;
    cudaGetSymbolAddress((void**)&hAh, g_hA_hi); cudaGetSymbolAddress((void**)&hAl, g_hA_lo);
    cudaGetSymbolAddress((void**)&hBh, g_hB_hi); cudaGetSymbolAddress((void**)&hBl, g_hB_lo);
    cudaGetSymbolAddress((void**)&xh,  g_x_hi);  cudaGetSymbolAddress((void**)&xl,  g_x_lo);
    cudaGetSymbolAddress((void**)&zh,  g_z_hi);  cudaGetSymbolAddress((void**)&zl,  g_z_lo);
    cudaGetSymbolAddress((void**)&z0,  g_z0);
    cudaGetSymbolAddress((void**)&w1h, g_w1_hi); cudaGetSymbolAddress((void**)&w1l, g_w1_lo);
    cudaGetSymbolAddress((void**)&w2h, g_w2_hi); cudaGetSymbolAddress((void**)&w2l, g_w2_lo);
    cudaGetSymbolAddress((void**)&d1h, g_d1_hi); cudaGetSymbolAddress((void**)&d1l, g_d1_lo);
    cudaGetSymbolAddress((void**)&d2h, g_d2_hi); cudaGetSymbolAddress((void**)&d2l, g_d2_lo);
    cudaGetSymbolAddress((void**)&d3h, g_d3_hi); cudaGetSymbolAddress((void**)&d3l, g_d3_lo);

    cudaFuncSetAttribute(wide_mma_kernel<64>,
        cudaFuncAttributeMaxDynamicSharedMemorySize, SM_WIDE);
    cudaFuncSetAttribute(wide_mma_kernel<32>,
        cudaFuncAttributeMaxDynamicSharedMemorySize, SM_WIDE);
    cudaFuncSetAttribute(wide_mma_kernel<512>,
        cudaFuncAttributeMaxDynamicSharedMemorySize, SM_WIDE);
    cudaFuncSetAttribute(out_mma_kernel,
        cudaFuncAttributeMaxDynamicSharedMemorySize, SM_OUT);

    // ---- prep (weights transposed+split, input split) ----
    prep_wT_kernel<<<(512 * 64 + 255) / 256, 256>>>(eW1, 64, 512, 64, 512 * 64, w1h, w1l);
    prep_wT_kernel<<<(512 * 512 + 255) / 256, 256>>>(eW2, 512, 512, 512, 512 * 512, w2h, w2l);
    prep_wT_kernel<<<(512 * 32 + 255) / 256, 256>>>(dW1, 8, 512, 32, 512 * 32, d1h, d1l);
    prep_wT_kernel<<<(512 * 512 + 255) / 256, 256>>>(dW2, 512, 512, 512, 512 * 512, d2h, d2l);
    prep_wT_kernel<<<(64 * 512 + 255) / 256, 256>>>(dW3, 512, 64, 512, 64 * 512, d3h, d3l);
    prep_x_kernel<<<(BATCH * 64) / 256, 256>>>(x0, xh, xl);

    const int nwide = BATCH / 64;    // 2048

    // ---- pipeline ----
    wide_mma_kernel<64><<<nwide, 512, SM_WIDE>>>(
        xh, xl, w1h, w1l, eb1, eg1, ebe1, hAh, hAl);
    wide_mma_kernel<512><<<nwide, 512, SM_WIDE>>>(
        hAh, hAl, w2h, w2l, eb2, eg2, ebe2, hBh, hBl);
    enc3_kernel<<<BATCH / 256, 256>>>(hBh, hBl, eW3, eb3, z0);
    integrate_kernel<<<BATCH / 256, 256>>>(z0, dtn, Xi, zh, zl);
    wide_mma_kernel<32><<<nwide, 512, SM_WIDE>>>(
        zh, zl, d1h, d1l, db1, dg1, dbe1, hAh, hAl);
    wide_mma_kernel<512><<<nwide, 512, SM_WIDE>>>(
        hAh, hAl, d2h, d2l, db2, dg2, dbe2, hBh, hBl);
    out_mma_kernel<<<BATCH / 128, 256, SM_OUT>>>(hBh, hBl, d3h, d3l, db3, out);
}